// round 16
// baseline (speedup 1.0000x reference)
#include <cuda_runtime.h>
#include <math.h>
#include <stdint.h>

#define NN 100000
#define EE 1600000
#define FF 512
#define HH 256

// ---------------- scratch (static device globals; no allocation) ------------
__device__ float g_B0[(size_t)NN * HH];
__device__ float g_B1[(size_t)NN * HH];
__device__ float g_B2[(size_t)NN * HH];
__device__ int   g_odeg[NN];
__device__ int   g_ideg[NN];
__device__ float g_nsrc[NN];
__device__ float g_ndst[NN];
__device__ float g_psum[HH];
__device__ float g_pmax[HH];
// CSR (in-edges grouped by dst)
__device__ int   g_rowstart[NN + 1];
__device__ int   g_cursor[NN];
__device__ int   g_csr_src[EE];
__device__ int   g_blksum[512];

// ---------------- helpers ---------------------------------------------------
__device__ __forceinline__ void atomicMaxFloat(float* addr, float v) {
    if (v >= 0.0f) atomicMax((int*)addr, __float_as_int(v));
    else           atomicMin((unsigned int*)addr, __float_as_uint(v));
}

__device__ __forceinline__ float leaky(float x) {
    return x > 0.0f ? x : 0.01f * x;
}

struct f8 { float a0, a1, a2, a3, a4, a5, a6, a7; };

// 256-bit global load (sm_100+): one LDG.E.256 per call
__device__ __forceinline__ f8 ldg256(const float* p) {
    f8 v;
    asm volatile("ld.global.nc.v8.f32 {%0,%1,%2,%3,%4,%5,%6,%7}, [%8];"
                 : "=f"(v.a0), "=f"(v.a1), "=f"(v.a2), "=f"(v.a3),
                   "=f"(v.a4), "=f"(v.a5), "=f"(v.a6), "=f"(v.a7)
                 : "l"(p));
    return v;
}
__device__ __forceinline__ void f8acc(f8& a, const f8& b) {
    a.a0 += b.a0; a.a1 += b.a1; a.a2 += b.a2; a.a3 += b.a3;
    a.a4 += b.a4; a.a5 += b.a5; a.a6 += b.a6; a.a7 += b.a7;
}

__device__ __forceinline__ uint16_t f2bf(float x) {
    uint16_t r;
    asm("cvt.rn.bf16.f32 %0, %1;" : "=h"(r) : "f"(x));
    return r;
}
__device__ __forceinline__ float bf2f(uint16_t b) {
    return __uint_as_float(((uint32_t)b) << 16);
}
__device__ __forceinline__ void bf16x3_pack(float x, float y, uint32_t& hi, uint32_t& lo) {
    uint16_t hx = f2bf(x);
    uint16_t hy = f2bf(y);
    uint16_t lx = f2bf(x - bf2f(hx));
    uint16_t ly = f2bf(y - bf2f(hy));
    hi = (uint32_t)hx | ((uint32_t)hy << 16);
    lo = (uint32_t)lx | ((uint32_t)ly << 16);
}

__device__ __forceinline__ void mma_bf16(float* d, const uint32_t* a, const uint32_t* b) {
    asm volatile(
        "mma.sync.aligned.m16n8k16.row.col.f32.bf16.bf16.f32 "
        "{%0,%1,%2,%3}, {%4,%5,%6,%7}, {%8,%9}, {%0,%1,%2,%3};\n"
        : "+f"(d[0]), "+f"(d[1]), "+f"(d[2]), "+f"(d[3])
        : "r"(a[0]), "r"(a[1]), "r"(a[2]), "r"(a[3]), "r"(b[0]), "r"(b[1]));
}

__device__ __forceinline__ void ldsm4(uint32_t* r, const uint32_t* p) {
    uint32_t a = (uint32_t)__cvta_generic_to_shared(p);
    asm volatile("ldmatrix.sync.aligned.m8n8.x4.shared.b16 {%0,%1,%2,%3}, [%4];"
                 : "=r"(r[0]), "=r"(r[1]), "=r"(r[2]), "=r"(r[3]) : "r"(a));
}

// ---------------- small kernels ---------------------------------------------
__global__ void k_prep() {
    int i = blockIdx.x * blockDim.x + threadIdx.x;
    if (i < NN) {
        g_odeg[i] = 0;
        g_ideg[i] = 0;
    }
}

__global__ void k_degree(const int* __restrict__ src, const int* __restrict__ dst) {
    int e = blockIdx.x * blockDim.x + threadIdx.x;
    if (e < EE) {
        atomicAdd(&g_odeg[src[e]], 1);
        atomicAdd(&g_ideg[dst[e]], 1);
    }
}

__global__ void k_norm() {
    int i = blockIdx.x * blockDim.x + threadIdx.x;
    if (i < NN) {
        g_nsrc[i] = rsqrtf(fmaxf((float)g_odeg[i], 1.0f));
        g_ndst[i] = rsqrtf(fmaxf((float)g_ideg[i], 1.0f));
    }
    if (blockIdx.x == 0 && threadIdx.x < HH) {
        g_psum[threadIdx.x] = 0.0f;
        g_pmax[threadIdx.x] = -INFINITY;
    }
}

// ---------------- CSR build ---------------------------------------------------
__global__ void k_scan1() {
    __shared__ int sh[256];
    int t = threadIdx.x;
    int i = blockIdx.x * 256 + t;
    int v = (i < NN) ? g_ideg[i] : 0;
    sh[t] = v;
    __syncthreads();
    #pragma unroll
    for (int off = 1; off < 256; off <<= 1) {
        int add = (t >= off) ? sh[t - off] : 0;
        __syncthreads();
        sh[t] += add;
        __syncthreads();
    }
    if (i < NN) g_rowstart[i] = sh[t] - v;
    if (t == 255) g_blksum[blockIdx.x] = sh[255];
}

__global__ void k_scan2(int nblk) {
    __shared__ int sh[512];
    int t = threadIdx.x;
    int v = (t < nblk) ? g_blksum[t] : 0;
    sh[t] = v;
    __syncthreads();
    #pragma unroll
    for (int off = 1; off < 512; off <<= 1) {
        int add = (t >= off) ? sh[t - off] : 0;
        __syncthreads();
        sh[t] += add;
        __syncthreads();
    }
    if (t < nblk) g_blksum[t] = sh[t] - v;
}

__global__ void k_scan3() {
    int i = blockIdx.x * blockDim.x + threadIdx.x;
    if (i < NN) {
        g_rowstart[i] += g_blksum[i >> 8];
        g_cursor[i] = 0;
    }
    if (i == 0) g_rowstart[NN] = EE;
}

__global__ void k_csr_fill(const int* __restrict__ src, const int* __restrict__ dst) {
    int e = blockIdx.x * blockDim.x + threadIdx.x;
    if (e < EE) {
        int d = dst[e];
        int pos = atomicAdd(&g_cursor[d], 1);
        g_csr_src[g_rowstart[d] + pos] = src[e];
    }
}

// ---------------- tensor-core GEMM (bf16x3, m16n8k16, double-buffered) -------
// C[:, n0:n0+128] = (A[N,K] * norm[row]) @ W[K, n0:n0+128]
// BM=128, BN=128, BK=16, 8 warps, warp tile 64(m) x 32(n). N-half via n0 param.
template <int K>
__global__ void __launch_bounds__(256, 2)
k_gemm_tc(const float* __restrict__ A, const float* __restrict__ W,
          const float* __restrict__ norm, float* __restrict__ C, int n0) {
    __shared__ __align__(16) uint32_t Ah[2][128][12];
    __shared__ __align__(16) uint32_t Al[2][128][12];
    __shared__ __align__(16) uint32_t Bh[2][8][136];
    __shared__ __align__(16) uint32_t Bl[2][8][136];

    const int tid  = threadIdx.x;
    const int lane = tid & 31;
    const int wid  = tid >> 5;
    const int wm   = wid & 1;        // m block of 64
    const int wn   = wid >> 1;       // n block of 32
    const int m0   = blockIdx.x * 128;

    const int a_r0 = tid >> 2;
    const int a_r1 = a_r0 + 64;
    const int a_c  = (tid & 3) << 2;
    const int a_k2 = (tid & 3) << 1;
    const int kb_e = (tid >> 5) << 1;
    const int b_k2 = tid >> 5;
    const int b_c  = (tid & 31) << 2;

    const float nrm0 = (m0 + a_r0 < NN) ? norm[m0 + a_r0] : 0.f;
    const float nrm1 = (m0 + a_r1 < NN) ? norm[m0 + a_r1] : 0.f;

    const int lm_r = (lane & 7) + ((lane >> 3) & 1) * 8;   // 0..15
    const int lm_c = (lane >> 4) * 4;                      // 0 or 4
    const int g    = lane >> 2;
    const int tig  = lane & 3;

    float acc[4][4][4];
    #pragma unroll
    for (int mt = 0; mt < 4; mt++)
        #pragma unroll
        for (int nt = 0; nt < 4; nt++)
            #pragma unroll
            for (int i = 0; i < 4; i++) acc[mt][nt][i] = 0.f;

    float4 pa0, pa1, pb0, pb1;

    #define LOAD_TILE(kt)                                                         \
        {                                                                         \
            int kbase = (kt) * 16;                                                \
            pa0 = (m0 + a_r0 < NN)                                                \
                ? *(const float4*)(A + (size_t)(m0 + a_r0) * K + kbase + a_c)     \
                : make_float4(0.f, 0.f, 0.f, 0.f);                                \
            pa1 = (m0 + a_r1 < NN)                                                \
                ? *(const float4*)(A + (size_t)(m0 + a_r1) * K + kbase + a_c)     \
                : make_float4(0.f, 0.f, 0.f, 0.f);                                \
            pb0 = *(const float4*)(W + (size_t)(kbase + kb_e) * HH + n0 + b_c);   \
            pb1 = *(const float4*)(W + (size_t)(kbase + kb_e + 1) * HH + n0 + b_c); \
        }

    #define STORE_TILE(buf)                                                       \
        {                                                                         \
            uint32_t h01, l01, h23, l23;                                          \
            bf16x3_pack(pa0.x * nrm0, pa0.y * nrm0, h01, l01);                    \
            bf16x3_pack(pa0.z * nrm0, pa0.w * nrm0, h23, l23);                    \
            *(uint2*)&Ah[buf][a_r0][a_k2] = make_uint2(h01, h23);                 \
            *(uint2*)&Al[buf][a_r0][a_k2] = make_uint2(l01, l23);                 \
            bf16x3_pack(pa1.x * nrm1, pa1.y * nrm1, h01, l01);                    \
            bf16x3_pack(pa1.z * nrm1, pa1.w * nrm1, h23, l23);                    \
            *(uint2*)&Ah[buf][a_r1][a_k2] = make_uint2(h01, h23);                 \
            *(uint2*)&Al[buf][a_r1][a_k2] = make_uint2(l01, l23);                 \
            uint32_t bh0, bl0, bh1, bl1, bh2, bl2, bh3, bl3;                      \
            bf16x3_pack(pb0.x, pb1.x, bh0, bl0);                                  \
            bf16x3_pack(pb0.y, pb1.y, bh1, bl1);                                  \
            bf16x3_pack(pb0.z, pb1.z, bh2, bl2);                                  \
            bf16x3_pack(pb0.w, pb1.w, bh3, bl3);                                  \
            *(uint4*)&Bh[buf][b_k2][b_c] = make_uint4(bh0, bh1, bh2, bh3);        \
            *(uint4*)&Bl[buf][b_k2][b_c] = make_uint4(bl0, bl1, bl2, bl3);        \
        }

    constexpr int KT = K / 16;

    LOAD_TILE(0);
    STORE_TILE(0);
    __syncthreads();

    for (int kt = 0; kt < KT; kt++) {
        const int cur = kt & 1;
        const int alt = cur ^ 1;

        if (kt + 1 < KT) LOAD_TILE(kt + 1);

        uint32_t ah[4][4];
        #pragma unroll
        for (int mt = 0; mt < 4; mt++)
            ldsm4(ah[mt], &Ah[cur][wm * 64 + mt * 16 + lm_r][lm_c]);

        uint32_t bh[4][2];
        #pragma unroll
        for (int nt = 0; nt < 4; nt++) {
            int nb = wn * 32 + nt * 8 + g;
            bh[nt][0] = Bh[cur][tig][nb];
            bh[nt][1] = Bh[cur][tig + 4][nb];
        }
        #pragma unroll
        for (int mt = 0; mt < 4; mt++)
            #pragma unroll
            for (int nt = 0; nt < 4; nt++)
                mma_bf16(acc[mt][nt], ah[mt], bh[nt]);

        uint32_t bl[4][2];
        #pragma unroll
        for (int nt = 0; nt < 4; nt++) {
            int nb = wn * 32 + nt * 8 + g;
            bl[nt][0] = Bl[cur][tig][nb];
            bl[nt][1] = Bl[cur][tig + 4][nb];
        }
        #pragma unroll
        for (int mt = 0; mt < 4; mt++)
            #pragma unroll
            for (int nt = 0; nt < 4; nt++)
                mma_bf16(acc[mt][nt], ah[mt], bl[nt]);

        uint32_t al[4][4];
        #pragma unroll
        for (int mt = 0; mt < 4; mt++)
            ldsm4(al[mt], &Al[cur][wm * 64 + mt * 16 + lm_r][lm_c]);
        #pragma unroll
        for (int mt = 0; mt < 4; mt++)
            #pragma unroll
            for (int nt = 0; nt < 4; nt++)
                mma_bf16(acc[mt][nt], al[mt], bh[nt]);

        if (kt + 1 < KT) STORE_TILE(alt);
        __syncthreads();
    }

    #pragma unroll
    for (int mt = 0; mt < 4; mt++) {
        #pragma unroll
        for (int nt = 0; nt < 4; nt++) {
            int row = m0 + wm * 64 + mt * 16 + g;
            int col = n0 + wn * 32 + nt * 8 + tig * 2;
            if (row < NN)
                *(float2*)(C + (size_t)row * HH + col) =
                    make_float2(acc[mt][nt][0], acc[mt][nt][1]);
            if (row + 8 < NN)
                *(float2*)(C + (size_t)(row + 8) * HH + col) =
                    make_float2(acc[mt][nt][2], acc[mt][nt][3]);
        }
    }
    #undef LOAD_TILE
    #undef STORE_TILE
}

// ---------------- CSR gather, column-split half pass, 256-bit loads ----------
// Processes 128 of 256 feature columns (floats [off*4, off*4+128)).
// One warp per node; half-warps each take alternate edges, one LDG.256 per
// lane per edge. POOL: accumulate pooled sum/max; store ONLY row *nidx.
template <bool POOL>
__global__ void __launch_bounds__(256)
k_gather_half(const float* __restrict__ X, float* __restrict__ O,
              const float* __restrict__ ndst, const float* __restrict__ bias,
              int off, const int* __restrict__ nidx) {
    __shared__ int   s_idx[8][128];
    __shared__ float s_sum[128];
    __shared__ float s_max[128];

    const int lane = threadIdx.x & 31;
    const int half = lane >> 4;               // 0 or 1 (edge selector)
    const int hl   = lane & 15;               // lane within half-warp
    const int wip  = threadIdx.x >> 5;
    const int n    = (blockIdx.x * blockDim.x + threadIdx.x) >> 5;

    if (POOL) {
        if (threadIdx.x < 128) {
            s_sum[threadIdx.x] = 0.0f;
            s_max[threadIdx.x] = -INFINITY;
        }
        __syncthreads();
    }

    const int fcol = off * 4 + hl * 8;

    f8 a = {0.f, 0.f, 0.f, 0.f, 0.f, 0.f, 0.f, 0.f};

    const bool valid = (n < NN);
    if (valid) {
        const int beg = g_rowstart[n];
        const int cnt = g_rowstart[n + 1] - beg;

        for (int base = 0; base < cnt; base += 128) {
            const int chunk = min(128, cnt - base);
            for (int j = lane; j < chunk; j += 32)
                s_idx[wip][j] = __ldg(&g_csr_src[beg + base + j]);
            __syncwarp();

            int j = 0;
            for (; j + 8 <= chunk; j += 8) {
                int e0 = s_idx[wip][j + half * 4 + 0];
                int e1 = s_idx[wip][j + half * 4 + 1];
                int e2 = s_idx[wip][j + half * 4 + 2];
                int e3 = s_idx[wip][j + half * 4 + 3];
                f8 v0 = ldg256(X + (size_t)e0 * HH + fcol);
                f8 v1 = ldg256(X + (size_t)e1 * HH + fcol);
                f8 v2 = ldg256(X + (size_t)e2 * HH + fcol);
                f8 v3 = ldg256(X + (size_t)e3 * HH + fcol);
                f8acc(a, v0); f8acc(a, v1); f8acc(a, v2); f8acc(a, v3);
            }
            for (; j + 2 <= chunk; j += 2) {
                int e0 = s_idx[wip][j + half];
                f8 v0 = ldg256(X + (size_t)e0 * HH + fcol);
                f8acc(a, v0);
            }
            if (j < chunk && half == 0) {
                int e0 = s_idx[wip][j];
                f8 v0 = ldg256(X + (size_t)e0 * HH + fcol);
                f8acc(a, v0);
            }
            __syncwarp();
        }
    }

    // combine half-warp partial sums (lane L and L+16 share columns)
    #pragma unroll
    for (int i = 0; i < 8; i++) {
        float* pv = &a.a0 + i;
        float other = __shfl_xor_sync(0xffffffffu, *pv, 16);
        *pv += other;
    }

    float o[8];
    if (valid) {
        const float nd = ndst[n];
        #pragma unroll
        for (int i = 0; i < 8; i++) {
            float bb = __ldg(&bias[fcol + i]);
            o[i] = leaky(fmaf((&a.a0)[i], nd, bb));
        }
        if (POOL) {
            // only the pooled stats + one row survive; store just that row
            if (half == 0 && n == __ldg(nidx)) {
                float4 o0 = make_float4(o[0], o[1], o[2], o[3]);
                float4 o1 = make_float4(o[4], o[5], o[6], o[7]);
                *(float4*)(O + (size_t)n * HH + fcol)     = o0;
                *(float4*)(O + (size_t)n * HH + fcol + 4) = o1;
            }
        } else {
            if (half == 0) {
                float4 o0 = make_float4(o[0], o[1], o[2], o[3]);
                float4 o1 = make_float4(o[4], o[5], o[6], o[7]);
                __stcs((float4*)(O + (size_t)n * HH + fcol), o0);
                __stcs((float4*)(O + (size_t)n * HH + fcol + 4), o1);
            }
        }
    }

    if (POOL) {
        if (valid && half == 0) {
            const int c = hl * 8;
            #pragma unroll
            for (int i = 0; i < 8; i++) {
                atomicAdd(&s_sum[c + i], o[i]);
                atomicMaxFloat(&s_max[c + i], o[i]);
            }
        }
        __syncthreads();
        if (threadIdx.x < 128) {
            atomicAdd(&g_psum[off * 4 + threadIdx.x], s_sum[threadIdx.x]);
            atomicMaxFloat(&g_pmax[off * 4 + threadIdx.x], s_max[threadIdx.x]);
        }
    }
}

// ---------------- generator head ---------------------------------------------
__global__ void k_final(const float* __restrict__ B, const int* __restrict__ node_index,
                        const float* __restrict__ b2,
                        const float* __restrict__ Wg, const float* __restrict__ bg,
                        const float* __restrict__ eps, float* __restrict__ out) {
    __shared__ float pooled[768];
    __shared__ float red[256];
    int t  = threadIdx.x;
    int ni = *node_index;

    pooled[t]       = g_psum[t];
    pooled[256 + t] = g_pmax[t];
    pooled[512 + t] = B[(size_t)ni * HH + t];
    __syncthreads();

    float fdv[4];
    #pragma unroll
    for (int o = 0; o < 4; o++) {
        int k = t + o * 256;
        float acc = bg[k];
        for (int i = 0; i < 768; i++)
            acc = fmaf(pooled[i], Wg[(size_t)i * 1024 + k], acc);
        fdv[o] = acc;
    }
    float mu1 = fdv[0],        mu2 = fdv[1];
    float sg1 = fabsf(fdv[2]), sg2 = fabsf(fdv[3]);
    float e1 = eps[t], e2 = eps[t + 256];
    float fn1 = fmaf(sg1, e1, mu1);
    float fn2 = fmaf(sg2, e2, mu2);

    out[t]              = fn1;  out[t + 256]        = fn2;
    out[512 + t]        = mu1;  out[512 + t + 256]  = mu2;
    out[1024 + t]       = sg1;  out[1024 + t + 256] = sg2;

    const float HALF_LOG_2PI = 0.9189385332046727f;
    float r1 = (fn1 - mu1) / sg1;
    float r2 = (fn2 - mu2) / sg2;
    float lp = (-0.5f * r1 * r1 - logf(sg1) - HALF_LOG_2PI)
             + (-0.5f * r2 * r2 - logf(sg2) - HALF_LOG_2PI);
    red[t] = lp;
    __syncthreads();
    for (int off = 128; off > 0; off >>= 1) {
        if (t < off) red[t] += red[t + off];
        __syncthreads();
    }
    if (t == 0) out[1536] = red[0] / 512.0f;
}

// ---------------- launcher ----------------------------------------------------
extern "C" void kernel_launch(void* const* d_in, const int* in_sizes, int n_in,
                              void* d_out, int out_size) {
    const float* feat = (const float*)d_in[0];
    const int*   src  = (const int*)d_in[1];
    const int*   dst  = (const int*)d_in[2];
    const int*   nidx = (const int*)d_in[3];
    const float* W1   = (const float*)d_in[4];
    const float* b1   = (const float*)d_in[5];
    const float* W2   = (const float*)d_in[6];
    const float* b2   = (const float*)d_in[7];
    const float* Wg   = (const float*)d_in[8];
    const float* bg   = (const float*)d_in[9];
    const float* eps  = (const float*)d_in[10];
    float* out = (float*)d_out;

    void *p0, *p1, *p2, *pns, *pnd;
    cudaGetSymbolAddress(&p0, g_B0);
    cudaGetSymbolAddress(&p1, g_B1);
    cudaGetSymbolAddress(&p2, g_B2);
    cudaGetSymbolAddress(&pns, g_nsrc);
    cudaGetSymbolAddress(&pnd, g_ndst);
    float* B0 = (float*)p0;
    float* B1 = (float*)p1;
    float* B2 = (float*)p2;
    float* nsrc = (float*)pns;
    float* ndst = (float*)pnd;

    const int DEG_BLKS  = (EE + 255) / 256;
    const int N_BLKS    = (NN + 255) / 256;      // 391
    const int GEMM_BLKS = (NN + 127) / 128;      // 782 (1-D, m only)
    const int GATH_BLKS = (NN + 7) / 8;          // one warp per node

    // prologue + CSR build (all before the producer/consumer chain)
    k_prep<<<N_BLKS, 256>>>();
    k_degree<<<DEG_BLKS, 256>>>(src, dst);
    k_norm<<<N_BLKS, 256>>>();
    k_scan1<<<N_BLKS, 256>>>();
    k_scan2<<<1, 512>>>(N_BLKS);
    k_scan3<<<N_BLKS, 256>>>();
    k_csr_fill<<<DEG_BLKS, 256>>>(src, dst);

    // layer 1: interleave GEMM N-halves with gather column-halves so each
    // gather reads a 51MB X-half that is L2-hot from the producing GEMM.
    k_gemm_tc<FF><<<GEMM_BLKS, 256>>>(feat, W1, nsrc, B0, 0);
    k_gather_half<false><<<GATH_BLKS, 256>>>(B0, B1, ndst, b1, 0, nidx);
    k_gemm_tc<FF><<<GEMM_BLKS, 256>>>(feat, W1, nsrc, B0, 128);
    k_gather_half<false><<<GATH_BLKS, 256>>>(B0, B1, ndst, b1, 32, nidx);

    // layer 2: same structure; pool-gather stores only row *nidx
    k_gemm_tc<HH><<<GEMM_BLKS, 256>>>(B1, W2, nsrc, B2, 0);
    k_gather_half<true><<<GATH_BLKS, 256>>>(B2, B0, ndst, b2, 0, nidx);
    k_gemm_tc<HH><<<GEMM_BLKS, 256>>>(B1, W2, nsrc, B2, 128);
    k_gather_half<true><<<GATH_BLKS, 256>>>(B2, B0, ndst, b2, 32, nidx);

    // head
    k_final<<<1, 256>>>(B0, nidx, b2, Wg, bg, eps, out);
}